// round 7
// baseline (speedup 1.0000x reference)
#include <cuda_runtime.h>
#include <cuda_fp16.h>
#include <cstdint>

#define D 512
#define BN 1024          // B*N = 8*128
#define NPAIR 128        // m per (b,n)
#define L2DIM 256        // W2 output width
#define KC 32            // K per chunk
#define CHUNKS 16        // 512/32
#define HROWB 80         // H smem row stride bytes (5*16B -> conflict-free ldmatrix)
#define WROWB 80         // W smem row stride bytes

// dyn smem layout (bytes)
#define OFF_AROW 0                   // 512*4 = 2048
#define OFF_B2   2048                // 1024
#define OFF_W3   3072                // 4096
#define OFF_PART 7168                // 128*16*4 = 8192
#define OFF_H    15360               // 2 * 128*80 = 20480
#define OFF_W    35840               // 2 * 256*80 = 40960
#define SMEM_TOTAL 76800

typedef unsigned long long ull;

// Scratch (allocation-free rule: __device__ globals)
__device__ float  g_A[BN * D];        // h1 + pc + b1   (indexed by n-row)
__device__ float  g_B[BN * D];        // h2 - pc        (indexed by m-row)
__device__ __half g_W2h[L2DIM * D];   // W2 transposed [l][k], fp16

// ---------------- helpers ----------------
__device__ __forceinline__ uint32_t smem_u32(const void* p) {
    uint32_t a;
    asm("{ .reg .u64 t; cvta.to.shared.u64 t, %1; cvt.u32.u64 %0, t; }" : "=r"(a) : "l"(p));
    return a;
}
__device__ __forceinline__ void cp_async16(uint32_t dst, const void* src) {
    asm volatile("cp.async.cg.shared.global [%0], [%1], 16;" :: "r"(dst), "l"(src) : "memory");
}
#define CP_COMMIT() asm volatile("cp.async.commit_group;" ::: "memory")
#define CP_WAIT0()  asm volatile("cp.async.wait_group 0;" ::: "memory")

__device__ __forceinline__ void ldsm4(uint32_t* r, uint32_t addr) {
    asm volatile("ldmatrix.sync.aligned.m8n8.x4.shared.b16 {%0,%1,%2,%3}, [%4];"
        : "=r"(r[0]), "=r"(r[1]), "=r"(r[2]), "=r"(r[3]) : "r"(addr));
}
__device__ __forceinline__ void mma_f16(float* d, const uint32_t* a, const uint32_t* b) {
    asm volatile(
        "mma.sync.aligned.m16n8k16.row.col.f32.f16.f16.f32 "
        "{%0,%1,%2,%3}, {%4,%5,%6,%7}, {%8,%9}, {%0,%1,%2,%3};"
        : "+f"(d[0]), "+f"(d[1]), "+f"(d[2]), "+f"(d[3])
        : "r"(a[0]), "r"(a[1]), "r"(a[2]), "r"(a[3]), "r"(b[0]), "r"(b[1]));
}
__device__ __forceinline__ uint32_t packh2(float x, float y) {
    __half2 h = __floats2half2_rn(x, y);
    return *reinterpret_cast<uint32_t*>(&h);
}
__device__ __forceinline__ void ffma2(ull &acc, ull a, ull b) {
    asm("fma.rn.f32x2 %0, %1, %2, %0;" : "+l"(acc) : "l"(a), "l"(b));
}
__device__ __forceinline__ ull pack2(float x, float y) {
    ull r;
    asm("mov.b64 %0, {%1, %2};" : "=l"(r) : "f"(x), "f"(y));
    return r;
}
__device__ __forceinline__ float2 unpack2(ull v) {
    float2 r;
    asm("mov.b64 {%0, %1}, %2;" : "=f"(r.x), "=f"(r.y) : "l"(v));
    return r;
}

// ================= Kernel 1 (merged): =================
// blocks y<32: A = f@W1a + pos@W1c + b1 ; Bt = f@W1b - pos@W1c   (f32x2 packed FMA)
// blocks y>=32: W2h[l][k] = fp16(W2[k][l])  (512 transpose blocks)
__global__ __launch_bounds__(256) void k1_precompute(
    const float* __restrict__ f, const float* __restrict__ pos,
    const float* __restrict__ W1, const float* __restrict__ b1,
    const float* __restrict__ W2)
{
    if (blockIdx.y >= 32) {
        int tb = (blockIdx.y - 32) * 8 + blockIdx.x;     // 0..511
        int idx = tb * 256 + threadIdx.x;                // k*256 + l, coalesced read
        int k = idx >> 8, l = idx & 255;
        g_W2h[l * D + k] = __float2half_rn(W2[idx]);
        return;
    }

    __shared__ __align__(16) float fT[32][33];
    __shared__ __align__(16) float Wa[32][64];
    __shared__ __align__(16) float Wb[32][64];

    const int t    = threadIdx.x;
    const int j0   = blockIdx.x * 64;
    const int row0 = blockIdx.y * 32;
    const int tx   = t & 15;
    const int ty   = t >> 4;
    const int c0   = tx * 4;
    const int r0   = ty * 2;

    ull accA[2][2], accB[2][2];
    #pragma unroll
    for (int r = 0; r < 2; r++)
        #pragma unroll
        for (int j = 0; j < 2; j++) { accA[r][j] = pack2(0.f, 0.f); accB[r][j] = pack2(0.f, 0.f); }

    for (int d0 = 0; d0 < D; d0 += 32) {
        #pragma unroll
        for (int i = 0; i < 4; i++) {
            int idx = t + i * 256;
            int r = idx >> 5, dd = idx & 31;
            fT[r][dd] = f[(row0 + r) * D + d0 + dd];
        }
        #pragma unroll
        for (int i = 0; i < 8; i++) {
            int idx = t + i * 256;
            int dd = idx >> 6, j = idx & 63;
            Wa[dd][j] = W1[(d0 + dd) * D + j0 + j];
            Wb[dd][j] = W1[(D + d0 + dd) * D + j0 + j];
        }
        __syncthreads();
        #pragma unroll
        for (int dd = 0; dd < 32; dd++) {
            ull f00 = pack2(fT[r0][dd], fT[r0][dd]);
            ull f11 = pack2(fT[r0 + 1][dd], fT[r0 + 1][dd]);
            ulonglong2 wa2 = *reinterpret_cast<const ulonglong2*>(&Wa[dd][c0]);
            ulonglong2 wb2 = *reinterpret_cast<const ulonglong2*>(&Wb[dd][c0]);
            ffma2(accA[0][0], f00, wa2.x); ffma2(accA[0][1], f00, wa2.y);
            ffma2(accA[1][0], f11, wa2.x); ffma2(accA[1][1], f11, wa2.y);
            ffma2(accB[0][0], f00, wb2.x); ffma2(accB[0][1], f00, wb2.y);
            ffma2(accB[1][0], f11, wb2.x); ffma2(accB[1][1], f11, wb2.y);
        }
        __syncthreads();
    }

    #pragma unroll
    for (int r = 0; r < 2; r++) {
        int row = row0 + r0 + r;
        float p0 = pos[row * 2 + 0];
        float p1 = pos[row * 2 + 1];
        #pragma unroll
        for (int jp = 0; jp < 2; jp++) {
            float2 a2 = unpack2(accA[r][jp]);
            float2 bb2 = unpack2(accB[r][jp]);
            float av[2] = {a2.x, a2.y}, bv[2] = {bb2.x, bb2.y};
            #pragma unroll
            for (int e = 0; e < 2; e++) {
                int jj = j0 + c0 + jp * 2 + e;
                float pcv = p0 * W1[(2 * D) * D + jj] + p1 * W1[(2 * D + 1) * D + jj];
                g_A[row * D + jj] = av[e] + pcv + b1[jj];
                g_B[row * D + jj] = bv[e] - pcv;
            }
        }
    }
}

// ================= Kernel 2: fp16 mma.sync GEMM per (b,n) =================
// 1024 blocks, 256 thr = 8 warps (2m x 4l). Warp tile 64x64 = 4x8 m16n8k16 frags
// (256 B LDSM traffic per HMMA vs 384 at 32x64). K=512 in 16 chunks of 32.
__global__ __launch_bounds__(256, 1) void k2_mma(
    const float* __restrict__ b2, const float* __restrict__ W3,
    const float* __restrict__ b3, float* __restrict__ out)
{
    extern __shared__ char smem[];
    const uint32_t sb = smem_u32(smem);
    float* aR   = (float*)(smem + OFF_AROW);
    float* b2s  = (float*)(smem + OFF_B2);
    float* w3s  = (float*)(smem + OFF_W3);
    float* part = (float*)(smem + OFF_PART);

    const int t = threadIdx.x, wid = t >> 5, lane = t & 31;
    const int wm = wid >> 2, wl = wid & 3;
    const int m0 = wm * 64, l0 = wl * 64;
    const int bn = blockIdx.x, b = bn >> 7;
    const float* Btb = g_B + (size_t)b * NPAIR * D;

    // staging roles
    const int hrow = t >> 1;            // H row (2 thr/row, 128 rows)
    const int hch  = (t & 1) * 2;       // 16B-chunk base (each thread: 2 chunks = 16 k)
    // W: each thread stages one full 256-row? no: row t covers 64B = 4 chunks

    aR[t] = g_A[bn * D + t];
    aR[t + 256] = g_A[bn * D + 256 + t];
    b2s[t] = b2[t];
    #pragma unroll
    for (int i = 0; i < 4; i++) w3s[t + i * 256] = W3[t + i * 256];
    __syncthreads();

    float acc[4][8][4];
    #pragma unroll
    for (int mt = 0; mt < 4; mt++)
        #pragma unroll
        for (int nt = 0; nt < 8; nt++)
            #pragma unroll
            for (int c = 0; c < 4; c++) acc[mt][nt][c] = 0.f;

    // ---- chunk 0: cp.async W (row t, 4 chunks), LDG+STS H ----
    {
        uint32_t wdst = sb + OFF_W + t * WROWB;
        #pragma unroll
        for (int j = 0; j < 4; j++)
            cp_async16(wdst + j * 16, &g_W2h[t * D + j * 8]);
        CP_COMMIT();

        const float* bp = &Btb[hrow * D + hch * 8];
        const float* ar = aR + hch * 8;
        uint32_t hp[8];
        #pragma unroll
        for (int q = 0; q < 4; q++) {
            float4 v = *reinterpret_cast<const float4*>(bp + q * 4);
            hp[2 * q]     = packh2(fmaxf(v.x + ar[q * 4 + 0], 0.f), fmaxf(v.y + ar[q * 4 + 1], 0.f));
            hp[2 * q + 1] = packh2(fmaxf(v.z + ar[q * 4 + 2], 0.f), fmaxf(v.w + ar[q * 4 + 3], 0.f));
        }
        uint32_t hdst = sb + OFF_H + hrow * HROWB + hch * 16;
        *reinterpret_cast<uint4*>((char*)smem + (hdst - sb)) = make_uint4(hp[0], hp[1], hp[2], hp[3]);
        *reinterpret_cast<uint4*>((char*)smem + (hdst - sb) + 16) = make_uint4(hp[4], hp[5], hp[6], hp[7]);
        CP_WAIT0();
        __syncthreads();
    }

    const int fr = lane & 15;            // ldmatrix row within 16
    const int fc = lane >> 4;            // ldmatrix 16B-chunk (0/1)

    for (int c = 0; c < CHUNKS; c++) {
        const int buf = c & 1;
        const bool more = (c + 1 < CHUNKS);
        float4 rB[4];

        if (more) {
            const int kn = (c + 1) * KC;
            uint32_t wdst = sb + OFF_W + (buf ^ 1) * 256 * WROWB + t * WROWB;
            #pragma unroll
            for (int j = 0; j < 4; j++)
                cp_async16(wdst + j * 16, &g_W2h[t * D + kn + j * 8]);
            CP_COMMIT();
            const float* bp = &Btb[hrow * D + kn + hch * 8];
            #pragma unroll
            for (int q = 0; q < 4; q++)
                rB[q] = *reinterpret_cast<const float4*>(bp + q * 4);
        }

        // ---- compute chunk c: 2 k-steps of 16 ----
        const uint32_t Hb = sb + OFF_H + buf * 128 * HROWB;
        const uint32_t Wb = sb + OFF_W + buf * 256 * WROWB;
        #pragma unroll
        for (int ks = 0; ks < 2; ks++) {
            const int kb = ks * 32 + fc * 16;   // byte offset within row
            uint32_t af[4][4];
            #pragma unroll
            for (int mt = 0; mt < 4; mt++)
                ldsm4(af[mt], Hb + (m0 + mt * 16 + fr) * HROWB + kb);
            uint32_t bf[4][4];
            #pragma unroll
            for (int g = 0; g < 4; g++)
                ldsm4(bf[g], Wb + (l0 + g * 16 + fr) * WROWB + kb);
            #pragma unroll
            for (int mt = 0; mt < 4; mt++)
                #pragma unroll
                for (int g = 0; g < 4; g++) {
                    uint32_t blo[2] = {bf[g][0], bf[g][2]};   // n rows g*16+0..7
                    uint32_t bhi[2] = {bf[g][1], bf[g][3]};   // n rows g*16+8..15
                    mma_f16(acc[mt][2 * g],     af[mt], blo);
                    mma_f16(acc[mt][2 * g + 1], af[mt], bhi);
                }
        }

        if (more) {
            const float* ar = aR + (c + 1) * KC + hch * 8;
            uint32_t hp[8];
            #pragma unroll
            for (int q = 0; q < 4; q++) {
                hp[2 * q]     = packh2(fmaxf(rB[q].x + ar[q * 4 + 0], 0.f), fmaxf(rB[q].y + ar[q * 4 + 1], 0.f));
                hp[2 * q + 1] = packh2(fmaxf(rB[q].z + ar[q * 4 + 2], 0.f), fmaxf(rB[q].w + ar[q * 4 + 3], 0.f));
            }
            char* hdst = (char*)smem + OFF_H + (buf ^ 1) * 128 * HROWB + hrow * HROWB + hch * 16;
            *reinterpret_cast<uint4*>(hdst) = make_uint4(hp[0], hp[1], hp[2], hp[3]);
            *reinterpret_cast<uint4*>(hdst + 16) = make_uint4(hp[4], hp[5], hp[6], hp[7]);
        }
        CP_WAIT0();
        __syncthreads();
    }

    // ---- epilogue: relu(acc + b2) @ W3, reduce over l-warps ----
    const int lr = lane >> 2, lc = lane & 3;
    #pragma unroll
    for (int mt = 0; mt < 4; mt++) {
        float o0[4] = {0.f, 0.f, 0.f, 0.f};
        float o1[4] = {0.f, 0.f, 0.f, 0.f};
        #pragma unroll
        for (int nt = 0; nt < 8; nt++) {
            int lcol = l0 + 8 * nt + 2 * lc;
            float vb0 = b2s[lcol], vb1 = b2s[lcol + 1];
            const float* w30 = &w3s[lcol * 4];
            const float* w31 = &w3s[(lcol + 1) * 4];
            float v00 = fmaxf(acc[mt][nt][0] + vb0, 0.f);
            float v01 = fmaxf(acc[mt][nt][1] + vb1, 0.f);
            float v10 = fmaxf(acc[mt][nt][2] + vb0, 0.f);
            float v11 = fmaxf(acc[mt][nt][3] + vb1, 0.f);
            #pragma unroll
            for (int o = 0; o < 4; o++) {
                o0[o] += v00 * w30[o] + v01 * w31[o];
                o1[o] += v10 * w30[o] + v11 * w31[o];
            }
        }
        #pragma unroll
        for (int off = 1; off <= 2; off <<= 1) {
            #pragma unroll
            for (int o = 0; o < 4; o++) {
                o0[o] += __shfl_xor_sync(0xffffffffu, o0[o], off);
                o1[o] += __shfl_xor_sync(0xffffffffu, o1[o], off);
            }
        }
        if (lc == 0) {
            int r0 = m0 + 16 * mt + lr;
            #pragma unroll
            for (int o = 0; o < 4; o++) {
                part[r0 * 16 + wl * 4 + o] = o0[o];
                part[(r0 + 8) * 16 + wl * 4 + o] = o1[o];
            }
        }
    }
    __syncthreads();

    if (t < 128) {
        float4 r;
        float s[4];
        #pragma unroll
        for (int o = 0; o < 4; o++) {
            s[o] = b3[o];
            #pragma unroll
            for (int w = 0; w < 4; w++) s[o] += part[t * 16 + w * 4 + o];
        }
        r.x = s[0]; r.y = s[1]; r.z = s[2]; r.w = s[3];
        *reinterpret_cast<float4*>(&out[((size_t)bn * NPAIR + t) * 4]) = r;
    }
}

extern "C" void kernel_launch(void* const* d_in, const int* in_sizes, int n_in,
                              void* d_out, int out_size)
{
    const float* f   = (const float*)d_in[0];
    const float* pos = (const float*)d_in[1];
    const float* W1  = (const float*)d_in[2];
    const float* b1  = (const float*)d_in[3];
    const float* W2  = (const float*)d_in[4];
    const float* b2  = (const float*)d_in[5];
    const float* W3  = (const float*)d_in[6];
    const float* b3  = (const float*)d_in[7];
    float* out = (float*)d_out;

    cudaFuncSetAttribute(k2_mma, cudaFuncAttributeMaxDynamicSharedMemorySize, SMEM_TOTAL);

    k1_precompute<<<dim3(8, 96), 256>>>(f, pos, W1, b1, W2);
    k2_mma<<<1024, 256, SMEM_TOTAL>>>(b2, W3, b3, out);
}

// round 8
// speedup vs baseline: 1.1412x; 1.1412x over previous
#include <cuda_runtime.h>
#include <cuda_fp16.h>
#include <cstdint>

#define D 512
#define BN 1024          // B*N = 8*128
#define NPAIR 128        // m per (b,n)
#define L2DIM 256        // W2 output width
#define KC 64            // K per chunk
#define CHUNKS 8         // 512/64
#define HROWB 144        // H smem row stride bytes (64 fp16 = 128B + 16 pad)
#define WROWB 144        // W smem row stride bytes

// dyn smem layout (bytes)
#define OFF_AROW 0                   // 512*4 = 2048
#define OFF_B2   2048                // 1024
#define OFF_W3   3072                // 4096
#define OFF_PART 7168                // 128*16*4 = 8192
#define OFF_H    15360               // 2 * 128*144 = 36864
#define OFF_W    52224               // 2 * 256*144 = 73728
#define SMEM_TOTAL 125952

typedef unsigned long long ull;

// Scratch (allocation-free rule: __device__ globals)
__device__ float  g_A[BN * D];        // h1 + pc + b1   (indexed by n-row)
__device__ float  g_B[BN * D];        // h2 - pc        (indexed by m-row)
__device__ __half g_W2h[L2DIM * D];   // W2 transposed [l][k], fp16

// ---------------- helpers ----------------
__device__ __forceinline__ uint32_t smem_u32(const void* p) {
    uint32_t a;
    asm("{ .reg .u64 t; cvta.to.shared.u64 t, %1; cvt.u32.u64 %0, t; }" : "=r"(a) : "l"(p));
    return a;
}
__device__ __forceinline__ void cp_async16(uint32_t dst, const void* src) {
    asm volatile("cp.async.cg.shared.global [%0], [%1], 16;" :: "r"(dst), "l"(src) : "memory");
}
#define CP_COMMIT() asm volatile("cp.async.commit_group;" ::: "memory")
#define CP_WAIT0()  asm volatile("cp.async.wait_group 0;" ::: "memory")

__device__ __forceinline__ void ldsm4(uint32_t* r, uint32_t addr) {
    asm volatile("ldmatrix.sync.aligned.m8n8.x4.shared.b16 {%0,%1,%2,%3}, [%4];"
        : "=r"(r[0]), "=r"(r[1]), "=r"(r[2]), "=r"(r[3]) : "r"(addr));
}
__device__ __forceinline__ void mma_f16(float* d, const uint32_t* a, const uint32_t* b) {
    asm volatile(
        "mma.sync.aligned.m16n8k16.row.col.f32.f16.f16.f32 "
        "{%0,%1,%2,%3}, {%4,%5,%6,%7}, {%8,%9}, {%0,%1,%2,%3};"
        : "+f"(d[0]), "+f"(d[1]), "+f"(d[2]), "+f"(d[3])
        : "r"(a[0]), "r"(a[1]), "r"(a[2]), "r"(a[3]), "r"(b[0]), "r"(b[1]));
}
__device__ __forceinline__ uint32_t packh2(float x, float y) {
    __half2 h = __floats2half2_rn(x, y);
    return *reinterpret_cast<uint32_t*>(&h);
}
__device__ __forceinline__ void ffma2(ull &acc, ull a, ull b) {
    asm("fma.rn.f32x2 %0, %1, %2, %0;" : "+l"(acc) : "l"(a), "l"(b));
}
__device__ __forceinline__ ull pack2(float x, float y) {
    ull r;
    asm("mov.b64 %0, {%1, %2};" : "=l"(r) : "f"(x), "f"(y));
    return r;
}
__device__ __forceinline__ float2 unpack2(ull v) {
    float2 r;
    asm("mov.b64 {%0, %1}, %2;" : "=f"(r.x), "=f"(r.y) : "l"(v));
    return r;
}

// ================= Kernel 1 (merged): =================
// blocks y<32: A = f@W1a + pos@W1c + b1 ; Bt = f@W1b - pos@W1c   (f32x2 packed FMA)
// blocks y>=32: smem-tiled transpose W2h[l][k] = fp16(W2[k][l]), 64x64 tiles
__global__ __launch_bounds__(256) void k1_precompute(
    const float* __restrict__ f, const float* __restrict__ pos,
    const float* __restrict__ W1, const float* __restrict__ b1,
    const float* __restrict__ W2)
{
    if (blockIdx.y >= 32) {
        // transpose tile: k-tile = blockIdx.x (8 of 64), l-tile = blockIdx.y-32 (4 of 64)
        __shared__ float tile[64][65];
        const int t = threadIdx.x;
        const int k0 = blockIdx.x * 64;
        const int l0 = (blockIdx.y - 32) * 64;
        #pragma unroll
        for (int i = 0; i < 16; i++) {
            int idx = i * 256 + t;
            int r = idx >> 6, cc = idx & 63;          // r = k offset, cc = l offset
            tile[r][cc] = W2[(k0 + r) * L2DIM + l0 + cc];
        }
        __syncthreads();
        #pragma unroll
        for (int j = 0; j < 2; j++) {
            int row = j * 32 + (t >> 3);              // l offset 0..63
            int ch  = t & 7;                          // 16B chunk (8 k values)
            uint32_t hp[4];
            #pragma unroll
            for (int q = 0; q < 4; q++)
                hp[q] = packh2(tile[ch * 8 + 2 * q][row], tile[ch * 8 + 2 * q + 1][row]);
            *reinterpret_cast<uint4*>(&g_W2h[(l0 + row) * D + k0 + ch * 8]) =
                make_uint4(hp[0], hp[1], hp[2], hp[3]);
        }
        return;
    }

    __shared__ __align__(16) float fT[32][33];
    __shared__ __align__(16) float Wa[32][64];
    __shared__ __align__(16) float Wb[32][64];

    const int t    = threadIdx.x;
    const int j0   = blockIdx.x * 64;
    const int row0 = blockIdx.y * 32;
    const int tx   = t & 15;
    const int ty   = t >> 4;
    const int c0   = tx * 4;
    const int r0   = ty * 2;

    ull accA[2][2], accB[2][2];
    #pragma unroll
    for (int r = 0; r < 2; r++)
        #pragma unroll
        for (int j = 0; j < 2; j++) { accA[r][j] = pack2(0.f, 0.f); accB[r][j] = pack2(0.f, 0.f); }

    for (int d0 = 0; d0 < D; d0 += 32) {
        #pragma unroll
        for (int i = 0; i < 4; i++) {
            int idx = t + i * 256;
            int r = idx >> 5, dd = idx & 31;
            fT[r][dd] = f[(row0 + r) * D + d0 + dd];
        }
        #pragma unroll
        for (int i = 0; i < 8; i++) {
            int idx = t + i * 256;
            int dd = idx >> 6, j = idx & 63;
            Wa[dd][j] = W1[(d0 + dd) * D + j0 + j];
            Wb[dd][j] = W1[(D + d0 + dd) * D + j0 + j];
        }
        __syncthreads();
        #pragma unroll
        for (int dd = 0; dd < 32; dd++) {
            ull f00 = pack2(fT[r0][dd], fT[r0][dd]);
            ull f11 = pack2(fT[r0 + 1][dd], fT[r0 + 1][dd]);
            ulonglong2 wa2 = *reinterpret_cast<const ulonglong2*>(&Wa[dd][c0]);
            ulonglong2 wb2 = *reinterpret_cast<const ulonglong2*>(&Wb[dd][c0]);
            ffma2(accA[0][0], f00, wa2.x); ffma2(accA[0][1], f00, wa2.y);
            ffma2(accA[1][0], f11, wa2.x); ffma2(accA[1][1], f11, wa2.y);
            ffma2(accB[0][0], f00, wb2.x); ffma2(accB[0][1], f00, wb2.y);
            ffma2(accB[1][0], f11, wb2.x); ffma2(accB[1][1], f11, wb2.y);
        }
        __syncthreads();
    }

    #pragma unroll
    for (int r = 0; r < 2; r++) {
        int row = row0 + r0 + r;
        float p0 = pos[row * 2 + 0];
        float p1 = pos[row * 2 + 1];
        #pragma unroll
        for (int jp = 0; jp < 2; jp++) {
            float2 a2 = unpack2(accA[r][jp]);
            float2 bb2 = unpack2(accB[r][jp]);
            float av[2] = {a2.x, a2.y}, bv[2] = {bb2.x, bb2.y};
            #pragma unroll
            for (int e = 0; e < 2; e++) {
                int jj = j0 + c0 + jp * 2 + e;
                float pcv = p0 * W1[(2 * D) * D + jj] + p1 * W1[(2 * D + 1) * D + jj];
                g_A[row * D + jj] = av[e] + pcv + b1[jj];
                g_B[row * D + jj] = bv[e] - pcv;
            }
        }
    }
}

// ================= Kernel 2: fp16 mma.sync GEMM per (b,n) =================
// 1024 blocks, 512 thr = 16 warps (4m x 4l). Warp tile 32x64 = 2x8 m16n8k16 frags.
// K=512 in 8 chunks of 64 (4 k-steps of 16): half the syncs of KC=32.
__global__ __launch_bounds__(512, 1) void k2_mma(
    const float* __restrict__ b2, const float* __restrict__ W3,
    const float* __restrict__ b3, float* __restrict__ out)
{
    extern __shared__ char smem[];
    const uint32_t sb = smem_u32(smem);
    float* aR   = (float*)(smem + OFF_AROW);
    float* b2s  = (float*)(smem + OFF_B2);
    float* w3s  = (float*)(smem + OFF_W3);
    float* part = (float*)(smem + OFF_PART);

    const int t = threadIdx.x, wid = t >> 5, lane = t & 31;
    const int wm = wid >> 2, wl = wid & 3;
    const int m0 = wm * 32, l0 = wl * 64;
    const int bn = blockIdx.x, b = bn >> 7;
    const float* Btb = g_B + (size_t)b * NPAIR * D;

    // staging roles
    const int hrow = t >> 2;            // H row (4 thr/row, 128 rows)
    const int hsub = t & 3;             // 16-k sub-block (0..3)
    const int wrow = t >> 1;            // W row (2 thr/row, 256 rows)
    const int wsub = t & 1;             // 32-k sub-block (0..1)

    aR[t] = g_A[bn * D + t];
    if (t < 256) b2s[t] = b2[t];
    #pragma unroll
    for (int i = 0; i < 2; i++) w3s[t + i * 512] = W3[t + i * 512];
    __syncthreads();

    float acc[2][8][4];
    #pragma unroll
    for (int mt = 0; mt < 2; mt++)
        #pragma unroll
        for (int nt = 0; nt < 8; nt++)
            #pragma unroll
            for (int c = 0; c < 4; c++) acc[mt][nt][c] = 0.f;

    // ---- stage chunk 0 ----
    {
        uint32_t wdst = sb + OFF_W + wrow * WROWB + wsub * 64;
        #pragma unroll
        for (int j = 0; j < 4; j++)
            cp_async16(wdst + j * 16, &g_W2h[wrow * D + wsub * 32 + j * 8]);
        CP_COMMIT();

        const float* bp = &Btb[hrow * D + hsub * 16];
        const float* ar = aR + hsub * 16;
        uint32_t hp[8];
        #pragma unroll
        for (int q = 0; q < 4; q++) {
            float4 v = *reinterpret_cast<const float4*>(bp + q * 4);
            hp[2 * q]     = packh2(fmaxf(v.x + ar[q * 4 + 0], 0.f), fmaxf(v.y + ar[q * 4 + 1], 0.f));
            hp[2 * q + 1] = packh2(fmaxf(v.z + ar[q * 4 + 2], 0.f), fmaxf(v.w + ar[q * 4 + 3], 0.f));
        }
        char* hdst = (char*)smem + OFF_H + hrow * HROWB + hsub * 32;
        *reinterpret_cast<uint4*>(hdst)      = make_uint4(hp[0], hp[1], hp[2], hp[3]);
        *reinterpret_cast<uint4*>(hdst + 16) = make_uint4(hp[4], hp[5], hp[6], hp[7]);
        CP_WAIT0();
        __syncthreads();
    }

    const int fr = lane & 15;            // ldmatrix row within 16
    const int fc = lane >> 4;            // ldmatrix 16B-chunk (0/1)

    for (int c = 0; c < CHUNKS; c++) {
        const int buf = c & 1;
        const bool more = (c + 1 < CHUNKS);
        float4 rB[4];

        if (more) {
            const int kn = (c + 1) * KC;
            uint32_t wdst = sb + OFF_W + (buf ^ 1) * 256 * WROWB + wrow * WROWB + wsub * 64;
            #pragma unroll
            for (int j = 0; j < 4; j++)
                cp_async16(wdst + j * 16, &g_W2h[wrow * D + kn + wsub * 32 + j * 8]);
            CP_COMMIT();
            const float* bp = &Btb[hrow * D + kn + hsub * 16];
            #pragma unroll
            for (int q = 0; q < 4; q++)
                rB[q] = *reinterpret_cast<const float4*>(bp + q * 4);
        }

        // ---- compute chunk c: 4 k-steps of 16 ----
        const uint32_t Hb = sb + OFF_H + buf * 128 * HROWB;
        const uint32_t Wb = sb + OFF_W + buf * 256 * WROWB;
        #pragma unroll
        for (int ks = 0; ks < 4; ks++) {
            const int kb = ks * 32 + fc * 16;   // byte offset within row
            uint32_t af[2][4];
            #pragma unroll
            for (int mt = 0; mt < 2; mt++)
                ldsm4(af[mt], Hb + (m0 + mt * 16 + fr) * HROWB + kb);
            uint32_t bf[4][4];
            #pragma unroll
            for (int g = 0; g < 4; g++)
                ldsm4(bf[g], Wb + (l0 + g * 16 + fr) * WROWB + kb);
            #pragma unroll
            for (int mt = 0; mt < 2; mt++)
                #pragma unroll
                for (int g = 0; g < 4; g++) {
                    uint32_t blo[2] = {bf[g][0], bf[g][2]};   // n rows g*16+0..7
                    uint32_t bhi[2] = {bf[g][1], bf[g][3]};   // n rows g*16+8..15
                    mma_f16(acc[mt][2 * g],     af[mt], blo);
                    mma_f16(acc[mt][2 * g + 1], af[mt], bhi);
                }
        }

        if (more) {
            const float* ar = aR + (c + 1) * KC + hsub * 16;
            uint32_t hp[8];
            #pragma unroll
            for (int q = 0; q < 4; q++) {
                hp[2 * q]     = packh2(fmaxf(rB[q].x + ar[q * 4 + 0], 0.f), fmaxf(rB[q].y + ar[q * 4 + 1], 0.f));
                hp[2 * q + 1] = packh2(fmaxf(rB[q].z + ar[q * 4 + 2], 0.f), fmaxf(rB[q].w + ar[q * 4 + 3], 0.f));
            }
            char* hdst = (char*)smem + OFF_H + (buf ^ 1) * 128 * HROWB + hrow * HROWB + hsub * 32;
            *reinterpret_cast<uint4*>(hdst)      = make_uint4(hp[0], hp[1], hp[2], hp[3]);
            *reinterpret_cast<uint4*>(hdst + 16) = make_uint4(hp[4], hp[5], hp[6], hp[7]);
        }
        CP_WAIT0();
        __syncthreads();
    }

    // ---- epilogue: relu(acc + b2) @ W3, reduce over l-warps ----
    const int lr = lane >> 2, lc = lane & 3;
    #pragma unroll
    for (int mt = 0; mt < 2; mt++) {
        float o0[4] = {0.f, 0.f, 0.f, 0.f};
        float o1[4] = {0.f, 0.f, 0.f, 0.f};
        #pragma unroll
        for (int nt = 0; nt < 8; nt++) {
            int lcol = l0 + 8 * nt + 2 * lc;
            float vb0 = b2s[lcol], vb1 = b2s[lcol + 1];
            const float* w30 = &w3s[lcol * 4];
            const float* w31 = &w3s[(lcol + 1) * 4];
            float v00 = fmaxf(acc[mt][nt][0] + vb0, 0.f);
            float v01 = fmaxf(acc[mt][nt][1] + vb1, 0.f);
            float v10 = fmaxf(acc[mt][nt][2] + vb0, 0.f);
            float v11 = fmaxf(acc[mt][nt][3] + vb1, 0.f);
            #pragma unroll
            for (int o = 0; o < 4; o++) {
                o0[o] += v00 * w30[o] + v01 * w31[o];
                o1[o] += v10 * w30[o] + v11 * w31[o];
            }
        }
        #pragma unroll
        for (int off = 1; off <= 2; off <<= 1) {
            #pragma unroll
            for (int o = 0; o < 4; o++) {
                o0[o] += __shfl_xor_sync(0xffffffffu, o0[o], off);
                o1[o] += __shfl_xor_sync(0xffffffffu, o1[o], off);
            }
        }
        if (lc == 0) {
            int r0 = m0 + 16 * mt + lr;
            #pragma unroll
            for (int o = 0; o < 4; o++) {
                part[r0 * 16 + wl * 4 + o] = o0[o];
                part[(r0 + 8) * 16 + wl * 4 + o] = o1[o];
            }
        }
    }
    __syncthreads();

    if (t < 128) {
        float4 r;
        float s[4];
        #pragma unroll
        for (int o = 0; o < 4; o++) {
            s[o] = b3[o];
            #pragma unroll
            for (int w = 0; w < 4; w++) s[o] += part[t * 16 + w * 4 + o];
        }
        r.x = s[0]; r.y = s[1]; r.z = s[2]; r.w = s[3];
        *reinterpret_cast<float4*>(&out[((size_t)bn * NPAIR + t) * 4]) = r;
    }
}

extern "C" void kernel_launch(void* const* d_in, const int* in_sizes, int n_in,
                              void* d_out, int out_size)
{
    const float* f   = (const float*)d_in[0];
    const float* pos = (const float*)d_in[1];
    const float* W1  = (const float*)d_in[2];
    const float* b1  = (const float*)d_in[3];
    const float* W2  = (const float*)d_in[4];
    const float* b2  = (const float*)d_in[5];
    const float* W3  = (const float*)d_in[6];
    const float* b3  = (const float*)d_in[7];
    float* out = (float*)d_out;

    cudaFuncSetAttribute(k2_mma, cudaFuncAttributeMaxDynamicSharedMemorySize, SMEM_TOTAL);

    k1_precompute<<<dim3(8, 36), 256>>>(f, pos, W1, b1, W2);
    k2_mma<<<1024, 512, SMEM_TOTAL>>>(b2, W3, b3, out);
}